// round 15
// baseline (speedup 1.0000x reference)
#include <cuda_runtime.h>
#include <cstdint>

// Problem constants (fixed by the reference)
#define Bsz      4096
#define Tmax     512
#define Vv       57
#define Ee       20
#define Hh       128
#define Oo       18

// Partitioning: 2 CTAs/SM, 16 warps/SM
#define RR       8            // batch rows per CTA
#define NT       256          // 64 col-pairs x 4 k-quarters
#define NCTAS    (Bsz / RR)   // 512

// h layout: value j at word (j>>5)*36 + (j&31); row stride 148 words.
// Quarter bases {0,36,72,108} -> banks {0,4,8,12}: LDS.128 conflict-free.
#define HROW     148
#define WORDOF(j) ((((j) >> 5) * 36) + ((j) & 31))

typedef unsigned long long ull;

__device__ float g_embW[Vv * Hh];   // embW[v][j] = emb[v]@W_ih[j] + b_ih[j] + b_hh[j]

// ---------------------------------------------------------------------------
__device__ __forceinline__ ull fma2(ull a, ull b, ull c) {
    ull d;
    asm("fma.rn.f32x2 %0, %1, %2, %3;" : "=l"(d) : "l"(a), "l"(b), "l"(c));
    return d;
}
__device__ __forceinline__ float hadd2(ull v) {
    float lo, hi;
    asm("mov.b64 {%0, %1}, %2;" : "=f"(lo), "=f"(hi) : "l"(v));
    return lo + hi;
}
__device__ __forceinline__ float ex2a(float x) {
    float y; asm("ex2.approx.f32 %0, %1;" : "=f"(y) : "f"(x)); return y;
}
__device__ __forceinline__ float rcpa(float x) {
    float y; asm("rcp.approx.f32 %0, %1;" : "=f"(y) : "f"(x)); return y;
}
// tanh(x) = 1 - 2/(1 + e^{2x}); saturates correctly at both infinities.
__device__ __forceinline__ float tanh_fast(float x) {
    float e = ex2a(x * 2.885390081777927f);        // e^{2x}
    return fmaf(-2.0f, rcpa(1.0f + e), 1.0f);
}

// ---------------------------------------------------------------------------
__global__ void embw_kernel(const float* __restrict__ emb,
                            const float* __restrict__ W_ih,
                            const float* __restrict__ b_ih,
                            const float* __restrict__ b_hh) {
    const int v = blockIdx.x, j = threadIdx.x;
    float s = b_ih[j] + b_hh[j];
    #pragma unroll
    for (int e = 0; e < Ee; e++) s = fmaf(emb[v * Ee + e], W_ih[j * Ee + e], s);
    g_embW[v * Hh + j] = s;
}

// ---------------------------------------------------------------------------
// ACCUM: accumulate 2 cols x 32 k (quarter q) over rows br..br+3 into A[8]
// (A[2r+c] packed over k). Each LDS.128 feeds 4 fma2, broadcast over p-lanes.
// ---------------------------------------------------------------------------
#define ACCUM(br, A)                                                           \
{                                                                              \
    _Pragma("unroll")                                                          \
    for (int i = 0; i < 8; i++) {                                              \
        ulonglong2 c0 = *(const ulonglong2*)(hc + ((br)+0)*HROW + q*36 + i*4); \
        ulonglong2 c1 = *(const ulonglong2*)(hc + ((br)+1)*HROW + q*36 + i*4); \
        ulonglong2 c2 = *(const ulonglong2*)(hc + ((br)+2)*HROW + q*36 + i*4); \
        ulonglong2 c3 = *(const ulonglong2*)(hc + ((br)+3)*HROW + q*36 + i*4); \
        A[0] = fma2(c0.x, w0[2*i], A[0]); A[0] = fma2(c0.y, w0[2*i+1], A[0]);  \
        A[1] = fma2(c0.x, w1[2*i], A[1]); A[1] = fma2(c0.y, w1[2*i+1], A[1]);  \
        A[2] = fma2(c1.x, w0[2*i], A[2]); A[2] = fma2(c1.y, w0[2*i+1], A[2]);  \
        A[3] = fma2(c1.x, w1[2*i], A[3]); A[3] = fma2(c1.y, w1[2*i+1], A[3]);  \
        A[4] = fma2(c2.x, w0[2*i], A[4]); A[4] = fma2(c2.y, w0[2*i+1], A[4]);  \
        A[5] = fma2(c2.x, w1[2*i], A[5]); A[5] = fma2(c2.y, w1[2*i+1], A[5]);  \
        A[6] = fma2(c3.x, w0[2*i], A[6]); A[6] = fma2(c3.y, w0[2*i+1], A[6]);  \
        A[7] = fma2(c3.x, w1[2*i], A[7]); A[7] = fma2(c3.y, w1[2*i+1], A[7]);  \
    }                                                                          \
}

// RED: reduce-scatter over the 4 q-lanes (masks 16, 8): lane q keeps row br+q,
// then tanh + store (+ predicated final capture). 6 shfl, 2 tanh per thread.
#define RED(A, br, EB, LEN, ROW)                                               \
{                                                                              \
    float v0 = hadd2(A[0]), v1 = hadd2(A[1]), v2 = hadd2(A[2]), v3 = hadd2(A[3]); \
    float v4 = hadd2(A[4]), v5 = hadd2(A[5]), v6 = hadd2(A[6]), v7 = hadd2(A[7]); \
    /* round 1 (mask 16 = q bit1): keep rows {0,1} or {2,3} */                 \
    float u0 = (b1 ? v4 : v0) + __shfl_xor_sync(~0u, b1 ? v0 : v4, 16);        \
    float u1 = (b1 ? v5 : v1) + __shfl_xor_sync(~0u, b1 ? v1 : v5, 16);        \
    float u2 = (b1 ? v6 : v2) + __shfl_xor_sync(~0u, b1 ? v2 : v6, 16);        \
    float u3 = (b1 ? v7 : v3) + __shfl_xor_sync(~0u, b1 ? v3 : v7, 16);        \
    /* round 2 (mask 8 = q bit0): keep even or odd row */                      \
    float s0 = (b0 ? u2 : u0) + __shfl_xor_sync(~0u, b0 ? u0 : u2, 8);         \
    float s1 = (b0 ? u3 : u1) + __shfl_xor_sync(~0u, b0 ? u1 : u3, 8);         \
    const float h0 = tanh_fast(s0 + (EB).x);                                   \
    const float h1 = tanh_fast(s1 + (EB).y);                                   \
    const float2 hv = make_float2(h0, h1);                                     \
    *(float2*)(hn + (ROW)*HROW + cw) = hv;                                     \
    if (t == (LEN) - 1)                                                        \
        *(float2*)(hfin + (ROW)*HROW + cw) = hv;                               \
}

// ---------------------------------------------------------------------------
__global__ void __launch_bounds__(NT, 2) rnn_kernel(
    const int*   __restrict__ x,      // [B, T]
    const int*   __restrict__ xlen,   // [B] sorted descending
    const float* __restrict__ W_hh,   // [H, H]
    const float* __restrict__ W_out,  // [O, H]
    const float* __restrict__ b_out,  // [O]
    float*       __restrict__ out)    // [B, O]
{
    __shared__ __align__(16) float hbuf[2][RR * HROW];   // 9472 B
    __shared__ __align__(16) float hfin[RR * HROW];      // 4736 B
    __shared__ float Wout_s[Oo * 129];                   // 9288 B
    __shared__ float logits_s[RR * Oo];
    __shared__ int   lens_s[RR];
    __shared__ int   toks[4][RR];                        // token ring (t mod 4)

    const int tid = threadIdx.x;
    const int l = tid & 31, w = tid >> 5;
    const int q  = l >> 3;              // k-quarter 0..3 (k in [q*32, q*32+32))
    const int p  = l & 7;               // col-pair within warp
    const int j0 = (w * 8 + p) * 2;     // first owned column
    const int cw = WORDOF(j0);          // gapped word of col j0 (j0 even)
    const bool b1 = (q & 2) != 0, b0 = (q & 1) != 0;
    const int rowA = q;                 // rows this thread finalizes
    const int rowB = 4 + q;
    const int row0 = blockIdx.x * RR;

    // ---- staging ----
    for (int i = tid; i < Oo * Hh; i += NT)
        Wout_s[(i / Hh) * 129 + (i % Hh)] = W_out[i];
    const int* xp = x + (row0 + (tid & 7)) * Tmax;       // valid for tid < 8
    if (tid < RR) {
        lens_s[tid] = xlen[row0 + tid];
        toks[0][tid] = xp[0];
        toks[1][tid] = xp[1];
    }
    for (int i = tid; i < RR * HROW; i += NT) hbuf[0][i] = 0.0f;
    __syncthreads();

    // ---- W_hh: 2 cols x 32 k -> 64 floats (32 ull) in registers ----
    ull w0[16], w1[16];
    {
        const ulonglong2* p0 = (const ulonglong2*)(W_hh + j0 * Hh + q * 32);
        const ulonglong2* p1 = (const ulonglong2*)(W_hh + (j0 + 1) * Hh + q * 32);
        #pragma unroll
        for (int i = 0; i < 8; i++) {
            ulonglong2 a = p0[i]; w0[2*i] = a.x; w0[2*i+1] = a.y;
            ulonglong2 b = p1[i]; w1[2*i] = b.x; w1[2*i+1] = b.y;
        }
    }

    const int maxlen = lens_s[0];           // lengths sorted descending
    const int lenA = lens_s[rowA];
    const int lenB = lens_s[rowB];

    // =========================== recurrence ===========================
    for (int t = 0; t < maxlen; t++) {
        const int cur = t & 1;
        const float* hc = hbuf[cur];
        float*       hn = hbuf[cur ^ 1];

        // token prefetch two steps ahead (ring slot (t+2)&3)
        if (tid < RR) {
            const int tt = min(t + 2, Tmax - 1);
            toks[(t + 2) & 3][tid] = xp[tt];
        }
        // eb for this step: issued early, L1-resident table, consumed at tanh
        const int ti = t & 3;
        const float2 eb0 = *(const float2*)&g_embW[toks[ti][rowA] * Hh + j0];
        const float2 eb1 = *(const float2*)&g_embW[toks[ti][rowB] * Hh + j0];

        {
            ull A[8] = {0,0,0,0,0,0,0,0};
            ACCUM(0, A)
            RED(A, 0, eb0, lenA, rowA)       // shfl/tanh latency hidden by:
        }
        {
            ull A[8] = {0,0,0,0,0,0,0,0};
            ACCUM(4, A)                       // <- this independent stream
            RED(A, 4, eb1, lenB, rowB)
        }
        __syncthreads();
    }

    // =========================== output head ===========================
    for (int idx = tid; idx < RR * Oo; idx += NT) {
        const int r = idx / Oo, o = idx % Oo;
        const float* hr = hfin + r * HROW;
        float s = b_out[o];
        #pragma unroll 4
        for (int k = 0; k < Hh; k++) {
            const float hv = hr[WORDOF(k)];
            s = fmaf(fmaxf(hv, 0.0f), Wout_s[o * 129 + k], s);
        }
        logits_s[idx] = s;
    }
    __syncthreads();

    if (tid < RR) {
        float m = -1e30f;
        #pragma unroll
        for (int o = 0; o < Oo; o++) m = fmaxf(m, logits_s[tid * Oo + o]);
        float se = 0.0f;
        #pragma unroll
        for (int o = 0; o < Oo; o++) se += expf(logits_s[tid * Oo + o] - m);
        const float lse = m + logf(se);
        #pragma unroll
        for (int o = 0; o < Oo; o++)
            out[(row0 + tid) * Oo + o] = logits_s[tid * Oo + o] - lse;
    }
}

// ---------------------------------------------------------------------------
extern "C" void kernel_launch(void* const* d_in, const int* in_sizes, int n_in,
                              void* d_out, int out_size) {
    const int*   x     = (const int*)  d_in[0];
    const int*   xlen  = (const int*)  d_in[1];
    const float* emb   = (const float*)d_in[2];
    const float* W_ih  = (const float*)d_in[3];
    const float* W_hh  = (const float*)d_in[4];
    const float* b_ih  = (const float*)d_in[5];
    const float* b_hh  = (const float*)d_in[6];
    const float* W_out = (const float*)d_in[7];
    const float* b_out = (const float*)d_in[8];

    embw_kernel<<<Vv, Hh>>>(emb, W_ih, b_ih, b_hh);
    rnn_kernel<<<NCTAS, NT>>>(x, xlen, W_hh, W_out, b_out, (float*)d_out);
}

// round 16
// speedup vs baseline: 1.0007x; 1.0007x over previous
#include <cuda_runtime.h>
#include <cstdint>

// Problem constants (fixed by the reference)
#define Bsz      4096
#define Tmax     512
#define Vv       57
#define Ee       20
#define Hh       128
#define Oo       18

// Partitioning: 2 CTAs/SM, 16 warps/SM
#define RR       8            // batch rows per CTA
#define NT       256          // 64 col-pairs x 4 k-quarters
#define NCTAS    (Bsz / RR)   // 512

// h layout: value j at word (j>>5)*36 + (j&31); row stride 148 words.
// Quarter bases {0,36,72,108} -> banks {0,4,8,12}: LDS.128 conflict-free.
#define HROW     148
#define WORDOF(j) ((((j) >> 5) * 36) + ((j) & 31))

typedef unsigned long long ull;

__device__ float g_embW[Vv * Hh];   // embW[v][j] = emb[v]@W_ih[j] + b_ih[j] + b_hh[j]

// ---------------------------------------------------------------------------
__device__ __forceinline__ ull fma2(ull a, ull b, ull c) {
    ull d;
    asm("fma.rn.f32x2 %0, %1, %2, %3;" : "=l"(d) : "l"(a), "l"(b), "l"(c));
    return d;
}
__device__ __forceinline__ float hadd2(ull v) {
    float lo, hi;
    asm("mov.b64 {%0, %1}, %2;" : "=f"(lo), "=f"(hi) : "l"(v));
    return lo + hi;
}
__device__ __forceinline__ float ex2a(float x) {
    float y; asm("ex2.approx.f32 %0, %1;" : "=f"(y) : "f"(x)); return y;
}
__device__ __forceinline__ float rcpa(float x) {
    float y; asm("rcp.approx.f32 %0, %1;" : "=f"(y) : "f"(x)); return y;
}
// tanh(x) = 1 - 2/(1 + e^{2x}); saturates correctly at both infinities.
__device__ __forceinline__ float tanh_fast(float x) {
    float e = ex2a(x * 2.885390081777927f);        // e^{2x}
    return fmaf(-2.0f, rcpa(1.0f + e), 1.0f);
}

// ---------------------------------------------------------------------------
__global__ void embw_kernel(const float* __restrict__ emb,
                            const float* __restrict__ W_ih,
                            const float* __restrict__ b_ih,
                            const float* __restrict__ b_hh) {
    const int v = blockIdx.x, j = threadIdx.x;
    float s = b_ih[j] + b_hh[j];
    #pragma unroll
    for (int e = 0; e < Ee; e++) s = fmaf(emb[v * Ee + e], W_ih[j * Ee + e], s);
    g_embW[v * Hh + j] = s;
}

// ---------------------------------------------------------------------------
// ACCUM: accumulate 2 cols x 32 k (quarter q) over rows br..br+3 into A[8]
// (A[2r+c] packed over k). Each LDS.128 feeds 4 fma2, broadcast over p-lanes.
// ---------------------------------------------------------------------------
#define ACCUM(br, A)                                                           \
{                                                                              \
    _Pragma("unroll")                                                          \
    for (int i = 0; i < 8; i++) {                                              \
        ulonglong2 c0 = *(const ulonglong2*)(hc + ((br)+0)*HROW + q*36 + i*4); \
        ulonglong2 c1 = *(const ulonglong2*)(hc + ((br)+1)*HROW + q*36 + i*4); \
        ulonglong2 c2 = *(const ulonglong2*)(hc + ((br)+2)*HROW + q*36 + i*4); \
        ulonglong2 c3 = *(const ulonglong2*)(hc + ((br)+3)*HROW + q*36 + i*4); \
        A[0] = fma2(c0.x, w0[2*i], A[0]); A[0] = fma2(c0.y, w0[2*i+1], A[0]);  \
        A[1] = fma2(c0.x, w1[2*i], A[1]); A[1] = fma2(c0.y, w1[2*i+1], A[1]);  \
        A[2] = fma2(c1.x, w0[2*i], A[2]); A[2] = fma2(c1.y, w0[2*i+1], A[2]);  \
        A[3] = fma2(c1.x, w1[2*i], A[3]); A[3] = fma2(c1.y, w1[2*i+1], A[3]);  \
        A[4] = fma2(c2.x, w0[2*i], A[4]); A[4] = fma2(c2.y, w0[2*i+1], A[4]);  \
        A[5] = fma2(c2.x, w1[2*i], A[5]); A[5] = fma2(c2.y, w1[2*i+1], A[5]);  \
        A[6] = fma2(c3.x, w0[2*i], A[6]); A[6] = fma2(c3.y, w0[2*i+1], A[6]);  \
        A[7] = fma2(c3.x, w1[2*i], A[7]); A[7] = fma2(c3.y, w1[2*i+1], A[7]);  \
    }                                                                          \
}

// RED: reduce-scatter over the 4 q-lanes (masks 16, 8): lane q keeps row br+q,
// then tanh + store (+ predicated final capture). 6 shfl, 2 tanh per thread.
#define RED(A, br, EB, LEN, ROW)                                               \
{                                                                              \
    float v0 = hadd2(A[0]), v1 = hadd2(A[1]), v2 = hadd2(A[2]), v3 = hadd2(A[3]); \
    float v4 = hadd2(A[4]), v5 = hadd2(A[5]), v6 = hadd2(A[6]), v7 = hadd2(A[7]); \
    /* round 1 (mask 16 = q bit1): keep rows {0,1} or {2,3} */                 \
    float u0 = (b1 ? v4 : v0) + __shfl_xor_sync(~0u, b1 ? v0 : v4, 16);        \
    float u1 = (b1 ? v5 : v1) + __shfl_xor_sync(~0u, b1 ? v1 : v5, 16);        \
    float u2 = (b1 ? v6 : v2) + __shfl_xor_sync(~0u, b1 ? v2 : v6, 16);        \
    float u3 = (b1 ? v7 : v3) + __shfl_xor_sync(~0u, b1 ? v3 : v7, 16);        \
    /* round 2 (mask 8 = q bit0): keep even or odd row */                      \
    float s0 = (b0 ? u2 : u0) + __shfl_xor_sync(~0u, b0 ? u0 : u2, 8);         \
    float s1 = (b0 ? u3 : u1) + __shfl_xor_sync(~0u, b0 ? u1 : u3, 8);         \
    const float h0 = tanh_fast(s0 + (EB).x);                                   \
    const float h1 = tanh_fast(s1 + (EB).y);                                   \
    const float2 hv = make_float2(h0, h1);                                     \
    *(float2*)(hn + (ROW)*HROW + cw) = hv;                                     \
    if (t == (LEN) - 1)                                                        \
        *(float2*)(hfin + (ROW)*HROW + cw) = hv;                               \
}

// ---------------------------------------------------------------------------
__global__ void __launch_bounds__(NT, 2) rnn_kernel(
    const int*   __restrict__ x,      // [B, T]
    const int*   __restrict__ xlen,   // [B] sorted descending
    const float* __restrict__ W_hh,   // [H, H]
    const float* __restrict__ W_out,  // [O, H]
    const float* __restrict__ b_out,  // [O]
    float*       __restrict__ out)    // [B, O]
{
    __shared__ __align__(16) float hbuf[2][RR * HROW];   // 9472 B
    __shared__ __align__(16) float hfin[RR * HROW];      // 4736 B
    __shared__ float Wout_s[Oo * 129];                   // 9288 B
    __shared__ float logits_s[RR * Oo];
    __shared__ int   lens_s[RR];
    __shared__ int   toks[4][RR];                        // token ring (t mod 4)

    const int tid = threadIdx.x;
    const int l = tid & 31, w = tid >> 5;
    const int q  = l >> 3;              // k-quarter 0..3 (k in [q*32, q*32+32))
    const int p  = l & 7;               // col-pair within warp
    const int j0 = (w * 8 + p) * 2;     // first owned column
    const int cw = WORDOF(j0);          // gapped word of col j0 (j0 even)
    const bool b1 = (q & 2) != 0, b0 = (q & 1) != 0;
    const int rowA = q;                 // rows this thread finalizes
    const int rowB = 4 + q;
    const int row0 = blockIdx.x * RR;

    // ---- staging ----
    for (int i = tid; i < Oo * Hh; i += NT)
        Wout_s[(i / Hh) * 129 + (i % Hh)] = W_out[i];
    const int* xp = x + (row0 + (tid & 7)) * Tmax;       // valid for tid < 8
    if (tid < RR) {
        lens_s[tid] = xlen[row0 + tid];
        toks[0][tid] = xp[0];
        toks[1][tid] = xp[1];
    }
    for (int i = tid; i < RR * HROW; i += NT) hbuf[0][i] = 0.0f;
    __syncthreads();

    // ---- W_hh: 2 cols x 32 k -> 64 floats (32 ull) in registers ----
    ull w0[16], w1[16];
    {
        const ulonglong2* p0 = (const ulonglong2*)(W_hh + j0 * Hh + q * 32);
        const ulonglong2* p1 = (const ulonglong2*)(W_hh + (j0 + 1) * Hh + q * 32);
        #pragma unroll
        for (int i = 0; i < 8; i++) {
            ulonglong2 a = p0[i]; w0[2*i] = a.x; w0[2*i+1] = a.y;
            ulonglong2 b = p1[i]; w1[2*i] = b.x; w1[2*i+1] = b.y;
        }
    }

    const int maxlen = lens_s[0];           // lengths sorted descending
    const int lenA = lens_s[rowA];
    const int lenB = lens_s[rowB];

    // =========================== recurrence ===========================
    for (int t = 0; t < maxlen; t++) {
        const int cur = t & 1;
        const float* hc = hbuf[cur];
        float*       hn = hbuf[cur ^ 1];

        // token prefetch two steps ahead (ring slot (t+2)&3)
        if (tid < RR) {
            const int tt = min(t + 2, Tmax - 1);
            toks[(t + 2) & 3][tid] = xp[tt];
        }
        // eb for this step: issued early, L1-resident table, consumed at tanh
        const int ti = t & 3;
        const float2 eb0 = *(const float2*)&g_embW[toks[ti][rowA] * Hh + j0];
        const float2 eb1 = *(const float2*)&g_embW[toks[ti][rowB] * Hh + j0];

        {
            ull A[8] = {0,0,0,0,0,0,0,0};
            ACCUM(0, A)
            RED(A, 0, eb0, lenA, rowA)       // shfl/tanh latency hidden by:
        }
        {
            ull A[8] = {0,0,0,0,0,0,0,0};
            ACCUM(4, A)                       // <- this independent stream
            RED(A, 4, eb1, lenB, rowB)
        }
        __syncthreads();
    }

    // =========================== output head ===========================
    for (int idx = tid; idx < RR * Oo; idx += NT) {
        const int r = idx / Oo, o = idx % Oo;
        const float* hr = hfin + r * HROW;
        float s = b_out[o];
        #pragma unroll 4
        for (int k = 0; k < Hh; k++) {
            const float hv = hr[WORDOF(k)];
            s = fmaf(fmaxf(hv, 0.0f), Wout_s[o * 129 + k], s);
        }
        logits_s[idx] = s;
    }
    __syncthreads();

    if (tid < RR) {
        float m = -1e30f;
        #pragma unroll
        for (int o = 0; o < Oo; o++) m = fmaxf(m, logits_s[tid * Oo + o]);
        float se = 0.0f;
        #pragma unroll
        for (int o = 0; o < Oo; o++) se += expf(logits_s[tid * Oo + o] - m);
        const float lse = m + logf(se);
        #pragma unroll
        for (int o = 0; o < Oo; o++)
            out[(row0 + tid) * Oo + o] = logits_s[tid * Oo + o] - lse;
    }
}

// ---------------------------------------------------------------------------
extern "C" void kernel_launch(void* const* d_in, const int* in_sizes, int n_in,
                              void* d_out, int out_size) {
    const int*   x     = (const int*)  d_in[0];
    const int*   xlen  = (const int*)  d_in[1];
    const float* emb   = (const float*)d_in[2];
    const float* W_ih  = (const float*)d_in[3];
    const float* W_hh  = (const float*)d_in[4];
    const float* b_ih  = (const float*)d_in[5];
    const float* b_hh  = (const float*)d_in[6];
    const float* W_out = (const float*)d_in[7];
    const float* b_out = (const float*)d_in[8];

    embw_kernel<<<Vv, Hh>>>(emb, W_ih, b_ih, b_hh);
    rnn_kernel<<<NCTAS, NT>>>(x, xlen, W_hh, W_out, b_out, (float*)d_out);
}